// round 15
// baseline (speedup 1.0000x reference)
#include <cuda_runtime.h>
#include <cuda_fp16.h>
#include <cstdint>

// GIN network. H=128 fixed; N, E, L, C, NG runtime-derived.
// R15: gather rebuilt with pairwise HADD2 pre-reduction + 32-bit addressing
//      (issue-bound per R14 profile). Capture slot now shows k_final0.
//      Rest identical to R14 (557.5us).

#define H 128
#define HW 64          // half2 words per row
#define MAXN 50176
#define MAXE 786432
#define MAXLAY 8
#define MAXG 128
#define NSLOT (3 * MAXLAY)
#define BN_EPS 1e-5f

__device__ uint32_t g_h16[MAXN * HW];
__device__ uint32_t g_x16[MAXN * HW];   // h_in16 -> neigh -> t -> u -> v
__device__ uint32_t g_w16[(2 * MAXLAY + 1) * 128 * 64];  // swizzled fp16 weights
__device__ float g_sum[NSLOT * H];
__device__ float g_sq[NSLOT * H];
__device__ float g_pooled[(MAXLAY + 1) * MAXG * H];
__device__ int g_off[MAXN + 1];
__device__ int g_cur[MAXN];
__device__ int g_bsum[64];
__device__ int g_csrc[MAXE];
__device__ volatile unsigned g_bar[MAXLAY];
__device__ volatile unsigned g_cbar[4];

__device__ __forceinline__ uint32_t pack_h2(float x0, float x1) {
    __half2 p = __floats2half2_rn(x0, x1);
    return *(uint32_t*)&p;
}
__device__ __forceinline__ float2 unpack_h2(uint32_t w) {
    return __half22float2(*(__half2*)&w);
}
__device__ __forceinline__ uint32_t hadd2_u(uint32_t a, uint32_t b) {
    __half2 r = __hadd2(*(__half2*)&a, *(__half2*)&b);
    return *(uint32_t*)&r;
}
__device__ __forceinline__ uint32_t bnrelu_h2(uint32_t v, uint32_t sc, uint32_t sh) {
    __half2 r = __hfma2(*(__half2*)&v, *(__half2*)&sc, *(__half2*)&sh);
    r = __hmax2(r, __float2half2_rn(0.f));
    return *(uint32_t*)&r;
}

// ---------------------------------------------------------------------------
// merged prologue: cvt h_in->x16 fp16, weight convert, zero pooled/stats/counts
__global__ void k_prep(const float* __restrict__ X,
                       const float* __restrict__ embW, const float* __restrict__ W1,
                       const float* __restrict__ W2, int L,
                       int cvtTot, int npool, int nstat, int ncnt) {
    int idx = blockIdx.x * blockDim.x + threadIdx.x;
    if (idx < cvtTot) {
        float2 f = ((const float2*)X)[idx];
        g_x16[idx] = pack_h2(f.x, f.y);
    }
    int wtot = (2 * L + 1) * 8192;
    if (idx < wtot) {
        int mat = idx >> 13;
        int r = idx & 8191;
        int n = r & 127;
        int kp = r >> 7;
        const float* W;
        if (mat == 0) W = embW;
        else if (mat <= L) W = W1 + (size_t)(mat - 1) * H * H;
        else W = W2 + (size_t)(mat - 1 - L) * H * H;
        float f0 = W[(size_t)(2 * kp) * H + n];
        float f1 = W[(size_t)(2 * kp + 1) * H + n];
        int phys = ((((kp >> 2) ^ (n & 7)) << 2) | (kp & 3));
        g_w16[mat * 8192 + n * 64 + phys] = pack_h2(f0, f1);
    }
    if (idx < npool) g_pooled[idx] = 0.f;
    if (idx < nstat) { g_sum[idx] = 0.f; g_sq[idx] = 0.f; }
    if (idx < ncnt) g_off[idx] = 0;
    if (idx < MAXLAY) g_bar[idx] = 0u;
    if (idx < 4) g_cbar[idx] = 0u;
}

// ---------------------------------------------------------------------------
// Fused CSR build: hist | bar | scan + block offsets | bar | fill.
__device__ __forceinline__ void csr_bar(int idx, int nblk) {
    __syncthreads();
    if (threadIdx.x == 0) {
        __threadfence();
        atomicAdd((unsigned*)&g_cbar[idx], 1u);
        while (g_cbar[idx] < (unsigned)nblk) __nanosleep(64);
    }
    __syncthreads();
}

__global__ void __launch_bounds__(1024) k_csr(const int* __restrict__ src,
                                              const int* __restrict__ dst,
                                              int N, int E) {
    __shared__ int s[1024];
    __shared__ int boff;
    const int tid = threadIdx.x;
    const int b = blockIdx.x;
    const int NB = gridDim.x;
    const int stride = NB * 1024;

    for (int e = b * 1024 + tid; e < E; e += stride)
        atomicAdd(&g_off[dst[e]], 1);
    csr_bar(0, NB);

    int idx = b * 1024 + tid;
    int v = (idx < N) ? g_off[idx] : 0;
    s[tid] = v;
    __syncthreads();
#pragma unroll
    for (int off = 1; off < 1024; off <<= 1) {
        int t = (tid >= off) ? s[tid - off] : 0;
        __syncthreads();
        s[tid] += t;
        __syncthreads();
    }
    int incl = s[tid];
    if (tid == 1023) g_bsum[b] = s[1023];
    csr_bar(1, NB);

    if (tid == 0) {
        int o = 0;
        for (int j = 0; j < b; j++) o += *(volatile int*)&g_bsum[j];
        boff = o;
    }
    __syncthreads();
    if (idx < N) {
        int o = incl - v + boff;
        g_off[idx] = o;
        g_cur[idx] = o;
    }
    if (b == 0 && tid == 0) g_off[N] = E;
    csr_bar(2, NB);

    for (int e = b * 1024 + tid; e < E; e += stride) {
        int pos = atomicAdd(&g_cur[dst[e]], 1);
        g_csrc[pos] = src[e];
    }
}

// ---------------------------------------------------------------------------
// gather: warp per 2 dst rows; pairwise HADD2 pre-reduction; 32-bit addressing.
__global__ void k_gather(const float* __restrict__ eps, int layer, int N) {
    int wid = (blockIdx.x * blockDim.x + threadIdx.x) >> 5;
    int lane = threadIdx.x & 31;
    int d0 = 2 * wid;
    if (d0 >= N) return;
    int d1 = d0 + 1;
    bool has1 = (d1 < N);
    float c0 = 1.f + eps[layer];
    const uint2* hp = (const uint2*)g_h16;

    uint2 w0 = hp[d0 * 32 + lane];
    float2 p00 = unpack_h2(w0.x), p01 = unpack_h2(w0.y);
    float4 acc0 = make_float4(p00.x * c0, p00.y * c0, p01.x * c0, p01.y * c0);
    float4 acc1 = make_float4(0.f, 0.f, 0.f, 0.f);
    if (has1) {
        uint2 w1 = hp[d1 * 32 + lane];
        float2 p10 = unpack_h2(w1.x), p11 = unpack_h2(w1.y);
        acc1 = make_float4(p10.x * c0, p10.y * c0, p11.x * c0, p11.y * c0);
    }

    int e0 = g_off[d0], e0e = g_off[d0 + 1];
    int e1 = has1 ? e0e : 0, e1e = has1 ? g_off[d1 + 1] : 0;

    // interleaved main loop: pair-sum in fp16, then one fp32 accumulate
    while (e0 + 1 < e0e && e1 + 1 < e1e) {
        int sA = g_csrc[e0], sB = g_csrc[e0 + 1];
        int sC = g_csrc[e1], sD = g_csrc[e1 + 1];
        uint2 vA = hp[sA * 32 + lane];
        uint2 vB = hp[sB * 32 + lane];
        uint2 vC = hp[sC * 32 + lane];
        uint2 vD = hp[sD * 32 + lane];
        uint32_t hx0 = hadd2_u(vA.x, vB.x), hy0 = hadd2_u(vA.y, vB.y);
        uint32_t hx1 = hadd2_u(vC.x, vD.x), hy1 = hadd2_u(vC.y, vD.y);
        float2 f0 = unpack_h2(hx0), f1 = unpack_h2(hy0);
        float2 f2 = unpack_h2(hx1), f3 = unpack_h2(hy1);
        acc0.x += f0.x; acc0.y += f0.y; acc0.z += f1.x; acc0.w += f1.y;
        acc1.x += f2.x; acc1.y += f2.y; acc1.z += f3.x; acc1.w += f3.y;
        e0 += 2; e1 += 2;
    }
    // remainder row 0
    for (; e0 + 1 < e0e; e0 += 2) {
        int sA = g_csrc[e0], sB = g_csrc[e0 + 1];
        uint2 vA = hp[sA * 32 + lane];
        uint2 vB = hp[sB * 32 + lane];
        uint32_t hx = hadd2_u(vA.x, vB.x), hy = hadd2_u(vA.y, vB.y);
        float2 f0 = unpack_h2(hx), f1 = unpack_h2(hy);
        acc0.x += f0.x; acc0.y += f0.y; acc0.z += f1.x; acc0.w += f1.y;
    }
    if (e0 < e0e) {
        int s = g_csrc[e0];
        uint2 v = hp[s * 32 + lane];
        float2 b0 = unpack_h2(v.x), b1 = unpack_h2(v.y);
        acc0.x += b0.x; acc0.y += b0.y; acc0.z += b1.x; acc0.w += b1.y;
    }
    // remainder row 1
    for (; e1 + 1 < e1e; e1 += 2) {
        int sA = g_csrc[e1], sB = g_csrc[e1 + 1];
        uint2 vA = hp[sA * 32 + lane];
        uint2 vB = hp[sB * 32 + lane];
        uint32_t hx = hadd2_u(vA.x, vB.x), hy = hadd2_u(vA.y, vB.y);
        float2 f0 = unpack_h2(hx), f1 = unpack_h2(hy);
        acc1.x += f0.x; acc1.y += f0.y; acc1.z += f1.x; acc1.w += f1.y;
    }
    if (e1 < e1e) {
        int s = g_csrc[e1];
        uint2 v = hp[s * 32 + lane];
        float2 b0 = unpack_h2(v.x), b1 = unpack_h2(v.y);
        acc1.x += b0.x; acc1.y += b0.y; acc1.z += b1.x; acc1.w += b1.y;
    }

    uint2 o0;
    o0.x = pack_h2(acc0.x, acc0.y);
    o0.y = pack_h2(acc0.z, acc0.w);
    ((uint2*)g_x16)[d0 * 32 + lane] = o0;
    if (has1) {
        uint2 o1;
        o1.x = pack_h2(acc1.x, acc1.y);
        o1.y = pack_h2(acc1.z, acc1.w);
        ((uint2*)g_x16)[d1 * 32 + lane] = o1;
    }
}

// ---------------------------------------------------------------------------
// Persistent pipelined tensor-core GEMM (fp16 in/out, fp32 accum). (R12)

#define SM_B 16384
#define SM_STAT 24576
#define GSMEM_TC ((24576 + 512) * 4)

#define MMA_F16(d, a0, a1, a2, a3, b0, b1)                                   \
    asm volatile(                                                            \
        "mma.sync.aligned.m16n8k16.row.col.f32.f16.f16.f32 "                 \
        "{%0,%1,%2,%3}, {%4,%5,%6,%7}, {%8,%9}, {%0,%1,%2,%3};"              \
        : "+f"(d[0]), "+f"(d[1]), "+f"(d[2]), "+f"(d[3])                     \
        : "r"(a0), "r"(a1), "r"(a2), "r"(a3), "r"(b0), "r"(b1))

#define LDSM4(r0, r1, r2, r3, addr)                                          \
    asm volatile("ldmatrix.sync.aligned.m8n8.x4.shared.b16 {%0,%1,%2,%3}, [%4];" \
                 : "=r"(r0), "=r"(r1), "=r"(r2), "=r"(r3) : "r"(addr))

__device__ __forceinline__ void prefetchA(uint32_t dstBase, const uint32_t* __restrict__ A16,
                                          int m0, int N, int tid) {
#pragma unroll
    for (int i = 0; i < 8; i++) {
        int idx = tid + i * 256;
        int row = idx >> 4;
        int c = idx & 15;
        int gm = m0 + row;
        if (gm > N - 1) gm = N - 1;
        uint32_t dst = dstBase + (uint32_t)(row * 64 + ((c ^ (row & 7)) << 2)) * 4;
        const uint32_t* src = A16 + (size_t)gm * HW + c * 4;
        asm volatile("cp.async.cg.shared.global [%0], [%1], 16;" :: "r"(dst), "l"(src));
    }
    asm volatile("cp.async.commit_group;");
}

__global__ void __launch_bounds__(256, 2) k_gemm_tc(
    const uint32_t* __restrict__ A16,
    const float* __restrict__ gamma, const float* __restrict__ beta, int ssIn,
    int wslot, const float* __restrict__ bias,
    uint32_t* __restrict__ C16, int outSlot, int N, int ntiles) {
    extern __shared__ uint32_t sm32[];
    uint32_t* Bs = sm32 + SM_B;
    float* ssum = (float*)(sm32 + SM_STAT);
    float* ssq = ssum + 128;
    uint32_t* scs = (uint32_t*)(ssq + 128);
    uint32_t* shs = scs + 64;

    const int tid = threadIdx.x;
    const int doBN = (ssIn >= 0);

    if (outSlot >= 0 && tid < 128) { ssum[tid] = 0.f; ssq[tid] = 0.f; }
    if (doBN && tid < 64) {
        float invN = 1.f / (float)N;
        int k0 = 2 * tid, k1 = k0 + 1;
        float m0 = g_sum[ssIn * H + k0] * invN;
        float v0 = g_sq[ssIn * H + k0] * invN - m0 * m0;
        float r0 = rsqrtf(v0 + BN_EPS);
        float sc0 = gamma[k0] * r0, sh0 = beta[k0] - m0 * sc0;
        float m1 = g_sum[ssIn * H + k1] * invN;
        float v1 = g_sq[ssIn * H + k1] * invN - m1 * m1;
        float r1 = rsqrtf(v1 + BN_EPS);
        float sc1 = gamma[k1] * r1, sh1 = beta[k1] - m1 * sc1;
        scs[tid] = pack_h2(sc0, sc1);
        shs[tid] = pack_h2(sh0, sh1);
    }

    {
        const uint4* Wm = (const uint4*)(g_w16 + wslot * 8192);
        uint4* Bd = (uint4*)Bs;
#pragma unroll
        for (int i = 0; i < 8; i++) Bd[tid + i * 256] = Wm[tid + i * 256];
    }

    const int w = tid >> 5;
    const int l = tid & 31;
    const int rb = (w & 3) * 32;
    const int cb = (w >> 2) * 64;
    const int c3 = l & 3;

    const uint32_t sbase = (uint32_t)__cvta_generic_to_shared(sm32);
    const uint32_t bBase = sbase + SM_B * 4;

    const int a_r = l & 15;
    const int a_c = l >> 4;
    const int b_nl = ((l >> 4) << 3) + (l & 7);
    const int b_kl = (l >> 3) & 1;

    int buf = 0;
    if (blockIdx.x < ntiles)
        prefetchA(sbase, A16, blockIdx.x * 128, N, tid);

    for (int tile = blockIdx.x; tile < ntiles; tile += gridDim.x) {
        const int m0 = tile * 128;
        int nxt = tile + gridDim.x;
        if (nxt < ntiles) {
            prefetchA(sbase + (buf ^ 1) * 8192 * 4, A16, nxt * 128, N, tid);
            asm volatile("cp.async.wait_group 1;");
        } else {
            asm volatile("cp.async.wait_group 0;");
        }
        __syncthreads();

        const uint32_t aBase = sbase + (uint32_t)buf * 8192 * 4;

        float acc[2][8][4];
#pragma unroll
        for (int mt = 0; mt < 2; mt++)
#pragma unroll
            for (int nt = 0; nt < 8; nt++)
#pragma unroll
                for (int j = 0; j < 4; j++) acc[mt][nt][j] = 0.f;

#pragma unroll
        for (int ks = 0; ks < 8; ks++) {
            uint32_t a[2][4];
#pragma unroll
            for (int mt = 0; mt < 2; mt++) {
                int row = rb + mt * 16 + a_r;
                int kc = ks * 2 + a_c;
                uint32_t addr = aBase + (row * 64 + ((kc ^ (row & 7)) << 2)) * 4;
                LDSM4(a[mt][0], a[mt][1], a[mt][2], a[mt][3], addr);
            }
            if (doBN) {
                uint32_t scA = scs[ks * 8 + c3], shA = shs[ks * 8 + c3];
                uint32_t scB = scs[ks * 8 + 4 + c3], shB = shs[ks * 8 + 4 + c3];
#pragma unroll
                for (int mt = 0; mt < 2; mt++) {
                    a[mt][0] = bnrelu_h2(a[mt][0], scA, shA);
                    a[mt][1] = bnrelu_h2(a[mt][1], scA, shA);
                    a[mt][2] = bnrelu_h2(a[mt][2], scB, shB);
                    a[mt][3] = bnrelu_h2(a[mt][3], scB, shB);
                }
            }
            uint32_t b[4][4];
#pragma unroll
            for (int np = 0; np < 4; np++) {
                int n = cb + np * 16 + b_nl;
                int kc = ks * 2 + b_kl;
                uint32_t addr = bBase + (n * 64 + ((kc ^ (n & 7)) << 2)) * 4;
                LDSM4(b[np][0], b[np][1], b[np][2], b[np][3], addr);
            }
#pragma unroll
            for (int mt = 0; mt < 2; mt++)
#pragma unroll
                for (int np = 0; np < 4; np++) {
                    MMA_F16(acc[mt][np * 2], a[mt][0], a[mt][1], a[mt][2], a[mt][3],
                            b[np][0], b[np][1]);
                    MMA_F16(acc[mt][np * 2 + 1], a[mt][0], a[mt][1], a[mt][2], a[mt][3],
                            b[np][2], b[np][3]);
                }
        }

#pragma unroll
        for (int mt = 0; mt < 2; mt++) {
            const int r0 = m0 + rb + mt * 16 + (l >> 2);
            const int r1 = r0 + 8;
#pragma unroll
            for (int nt = 0; nt < 8; nt++) {
                int c0 = cb + nt * 8 + (l & 3) * 2;
                float bb0 = bias[c0], bb1 = bias[c0 + 1];
                float v0 = acc[mt][nt][0] + bb0;
                float v1 = acc[mt][nt][1] + bb1;
                float v2 = acc[mt][nt][2] + bb0;
                float v3 = acc[mt][nt][3] + bb1;
                int wIdx = c0 >> 1;
                if (r0 < N) C16[(size_t)r0 * HW + wIdx] = pack_h2(v0, v1);
                if (r1 < N) C16[(size_t)r1 * HW + wIdx] = pack_h2(v2, v3);
                if (outSlot >= 0) {
                    float s0 = (r0 < N ? v0 : 0.f) + (r1 < N ? v2 : 0.f);
                    float s1 = (r0 < N ? v1 : 0.f) + (r1 < N ? v3 : 0.f);
                    float q0 = (r0 < N ? v0 * v0 : 0.f) + (r1 < N ? v2 * v2 : 0.f);
                    float q1 = (r0 < N ? v1 * v1 : 0.f) + (r1 < N ? v3 * v3 : 0.f);
#pragma unroll
                    for (int off = 16; off >= 4; off >>= 1) {
                        s0 += __shfl_down_sync(0xffffffffu, s0, off);
                        s1 += __shfl_down_sync(0xffffffffu, s1, off);
                        q0 += __shfl_down_sync(0xffffffffu, q0, off);
                        q1 += __shfl_down_sync(0xffffffffu, q1, off);
                    }
                    if (l < 4) {
                        atomicAdd(&ssum[c0], s0);
                        atomicAdd(&ssum[c0 + 1], s1);
                        atomicAdd(&ssq[c0], q0);
                        atomicAdd(&ssq[c0 + 1], q1);
                    }
                }
            }
        }
        __syncthreads();
        buf ^= 1;
    }
    if (outSlot >= 0) {
        if (tid < 128) {
            atomicAdd(&g_sum[outSlot * H + tid], ssum[tid]);
            atomicAdd(&g_sq[outSlot * H + tid], ssq[tid]);
        }
    }
}

// ---------------------------------------------------------------------------
// Fused passv + final (persistent, grid barrier); h in fp16 only.
__global__ void __launch_bounds__(128) k_pf(
    uint32_t* __restrict__ X16, const float* __restrict__ snorm,
    const float* __restrict__ ga, const float* __restrict__ ba,
    const float* __restrict__ gl, const float* __restrict__ bl,
    const int* __restrict__ gids, int sIn, int sOut, int layer,
    int rep, int NG, int N, int nblk) {
    const int w = threadIdx.x & 63;
    const int rh = threadIdx.x >> 6;
    const int c0 = 2 * w, c1 = c0 + 1;
    const float invN = 1.f / (float)N;

    const int chunk = (N + nblk - 1) / nblk;
    const int nb = blockIdx.x * chunk;
    const int ne = (nb + chunk < N) ? nb + chunk : N;

    {
        float m0 = g_sum[sIn * H + c0] * invN;
        float v0 = g_sq[sIn * H + c0] * invN - m0 * m0;
        float r0 = rsqrtf(v0 + BN_EPS);
        float sc0 = ga[c0] * r0, sh0 = ba[c0] - m0 * sc0;
        float m1 = g_sum[sIn * H + c1] * invN;
        float v1 = g_sq[sIn * H + c1] * invN - m1 * m1;
        float r1 = rsqrtf(v1 + BN_EPS);
        float sc1 = ga[c1] * r1, sh1 = ba[c1] - m1 * sc1;

        float s0 = 0.f, s1 = 0.f, q0 = 0.f, q1 = 0.f;
        for (int n = nb + rh; n < ne; n += 2) {
            float sn = snorm[n];
            float2 f = unpack_h2(X16[(size_t)n * HW + w]);
            float x0 = fmaxf(sc0 * f.x + sh0, 0.f) * sn;
            float x1 = fmaxf(sc1 * f.y + sh1, 0.f) * sn;
            X16[(size_t)n * HW + w] = pack_h2(x0, x1);
            s0 += x0; s1 += x1; q0 += x0 * x0; q1 += x1 * x1;
        }
        atomicAdd(&g_sum[sOut * H + c0], s0);
        atomicAdd(&g_sum[sOut * H + c1], s1);
        atomicAdd(&g_sq[sOut * H + c0], q0);
        atomicAdd(&g_sq[sOut * H + c1], q1);
    }

    __syncthreads();
    if (threadIdx.x == 0) {
        __threadfence();
        atomicAdd((unsigned*)&g_bar[layer], 1u);
        while (g_bar[layer] < (unsigned)nblk) __nanosleep(64);
    }
    __syncthreads();

    {
        float sum0 = __ldcg((const float*)&g_sum[sOut * H + c0]);
        float sum1 = __ldcg((const float*)&g_sum[sOut * H + c1]);
        float sq0 = __ldcg((const float*)&g_sq[sOut * H + c0]);
        float sq1 = __ldcg((const float*)&g_sq[sOut * H + c1]);
        float m0 = sum0 * invN;
        float v0 = sq0 * invN - m0 * m0;
        float r0 = rsqrtf(v0 + BN_EPS);
        float sc0 = gl[c0] * r0, sh0 = bl[c0] - m0 * sc0;
        float m1 = sum1 * invN;
        float v1 = sq1 * invN - m1 * m1;
        float r1 = rsqrtf(v1 + BN_EPS);
        float sc1 = gl[c1] * r1, sh1 = bl[c1] - m1 * sc1;

        float* pooled = g_pooled + (size_t)rep * NG * H;
        int n = nb + rh;
        if (n < ne) {
            float a0 = 0.f, a1 = 0.f;
            int curg = gids[n];
            for (; n < ne; n += 2) {
                int g = gids[n];
                if (g != curg) {
                    atomicAdd(&pooled[(size_t)curg * H + c0], a0);
                    atomicAdd(&pooled[(size_t)curg * H + c1], a1);
                    a0 = 0.f; a1 = 0.f;
                    curg = g;
                }
                float2 hv = unpack_h2(g_h16[(size_t)n * HW + w]);
                float2 f = unpack_h2(X16[(size_t)n * HW + w]);
                hv.x += fmaxf(sc0 * f.x + sh0, 0.f);
                hv.y += fmaxf(sc1 * f.y + sh1, 0.f);
                g_h16[(size_t)n * HW + w] = pack_h2(hv.x, hv.y);
                a0 += hv.x; a1 += hv.y;
            }
            atomicAdd(&pooled[(size_t)curg * H + c0], a0);
            atomicAdd(&pooled[(size_t)curg * H + c1], a1);
        }
    }
}

// standalone pool for hidden_rep[0] (reads fp16 h)
__global__ void k_final0(const int* __restrict__ gids, int NG, int N) {
    int w = threadIdx.x & 63;
    int rh = threadIdx.x >> 6;
    int c0 = 2 * w, c1 = c0 + 1;
    int n0 = blockIdx.x * 128 + rh;
    if (n0 >= N) return;
    int nend = blockIdx.x * 128 + 128;
    if (nend > N) nend = N;
    float a0 = 0.f, a1 = 0.f;
    int curg = gids[n0];
    for (int n = n0; n < nend; n += 2) {
        int g = gids[n];
        if (g != curg) {
            atomicAdd(&g_pooled[(size_t)curg * H + c0], a0);
            atomicAdd(&g_pooled[(size_t)curg * H + c1], a1);
            a0 = 0.f; a1 = 0.f;
            curg = g;
        }
        float2 hv = unpack_h2(g_h16[(size_t)n * HW + w]);
        a0 += hv.x; a1 += hv.y;
    }
    atomicAdd(&g_pooled[(size_t)curg * H + c0], a0);
    atomicAdd(&g_pooled[(size_t)curg * H + c1], a1);
}

__global__ void k_score(const float* __restrict__ predW, const float* __restrict__ predb,
                        float* __restrict__ out, int NG, int C, int nrep) {
    int g = blockIdx.x;
    int c = threadIdx.x;
    if (c >= C) return;
    float s = 0.f;
    for (int rep = 0; rep < nrep; rep++) {
        const float* pl = g_pooled + ((size_t)rep * NG + g) * H;
        const float* W = predW + (size_t)rep * H * C;
        float acc = 0.f;
        for (int k = 0; k < H; k++) acc = fmaf(pl[k], W[k * C + c], acc);
        s += acc + predb[rep * C + c];
    }
    out[g * C + c] = s;
}

// ---------------------------------------------------------------------------
extern "C" void kernel_launch(void* const* d_in, const int* in_sizes, int n_in,
                              void* d_out, int out_size) {
    const float* h_in  = (const float*)d_in[0];
    const float* snorm = (const float*)d_in[1];
    const int* esrc    = (const int*)d_in[2];
    const int* edst    = (const int*)d_in[3];
    const int* gids    = (const int*)d_in[4];
    const float* embW  = (const float*)d_in[5];
    const float* embb  = (const float*)d_in[6];
    const float* eps   = (const float*)d_in[7];
    const float* W1    = (const float*)d_in[8];
    const float* b1    = (const float*)d_in[9];
    const float* g1    = (const float*)d_in[10];
    const float* be1   = (const float*)d_in[11];
    const float* W2    = (const float*)d_in[12];
    const float* b2    = (const float*)d_in[13];
    const float* ga    = (const float*)d_in[14];
    const float* ba    = (const float*)d_in[15];
    const float* gl    = (const float*)d_in[16];
    const float* bl    = (const float*)d_in[17];
    const float* predW = (const float*)d_in[18];
    const float* predb = (const float*)d_in[19];
    float* out = (float*)d_out;

    int N = in_sizes[0] / H;
    int E = in_sizes[2];
    int L = in_sizes[7];
    int C = in_sizes[19] / (L + 1);
    int NG = out_size / C;
    int NB = (N + 1023) / 1024;

    cudaFuncSetAttribute(k_gemm_tc, cudaFuncAttributeMaxDynamicSharedMemorySize, GSMEM_TC);

    uint32_t *p_h16, *p_x16;
    cudaGetSymbolAddress((void**)&p_h16, g_h16);
    cudaGetSymbolAddress((void**)&p_x16, g_x16);

    int smCount = 148, occBlocks = 8;
    cudaDeviceGetAttribute(&smCount, cudaDevAttrMultiProcessorCount, 0);
    cudaOccupancyMaxActiveBlocksPerMultiprocessor(&occBlocks, k_pf, 128, 0);
    if (occBlocks < 1) occBlocks = 1;
    if (occBlocks > 12) occBlocks = 12;
    int nblk = smCount * occBlocks;

    int ntiles = (N + 127) / 128;
    int gemmGrid = 2 * smCount;
    if (gemmGrid > ntiles) gemmGrid = ntiles;
    int rowGrid = ntiles;

    int npool = (L + 1) * NG * H;
    int nstat = 3 * L * H;
    int ncnt = N + 1;
    int cvtTot = N * HW;

    int gwarps = (N + 1) / 2;
    int gblocks = (gwarps * 32 + 255) / 256;

    // Launch order: index 3 (ncu capture slot) = k_final0.
    k_prep<<<(cvtTot + 255) / 256, 256>>>(h_in, embW, W1, W2, L,
                                          cvtTot, npool, nstat, ncnt);      // 0
    k_csr<<<NB, 1024>>>(esrc, edst, N, E);                                  // 1
    k_gemm_tc<<<gemmGrid, 256, GSMEM_TC>>>(p_x16, nullptr, nullptr, -1,
                                           0, embb, p_h16, -1, N, ntiles);  // 2 (emb)
    k_final0<<<rowGrid, 128>>>(gids, NG, N);                                // 3 <- capture
    k_gather<<<gblocks, 256>>>(eps, 0, N);                                  // 4

    for (int i = 0; i < L; i++) {
        int s0 = 3 * i, s1 = 3 * i + 1, s2 = 3 * i + 2;
        k_gemm_tc<<<gemmGrid, 256, GSMEM_TC>>>(p_x16, nullptr, nullptr, -1,
                                               1 + i, b1 + i * H,
                                               p_x16, s0, N, ntiles);
        k_gemm_tc<<<gemmGrid, 256, GSMEM_TC>>>(p_x16, g1 + i * H, be1 + i * H, s0,
                                               1 + L + i, b2 + i * H,
                                               p_x16, s1, N, ntiles);
        k_pf<<<nblk, 128>>>(p_x16, snorm, ga + i * H, ba + i * H,
                            gl + i * H, bl + i * H, gids,
                            s1, s2, i, i + 1, NG, N, nblk);
        if (i + 1 < L)
            k_gather<<<gblocks, 256>>>(eps, i + 1, N);
    }

    k_score<<<NG, 32>>>(predW, predb, out, NG, C, L + 1);
}

// round 16
// speedup vs baseline: 1.0510x; 1.0510x over previous
#include <cuda_runtime.h>
#include <cuda_fp16.h>
#include <cstdint>

// GIN network. H=128 fixed; N, E, L, C, NG runtime-derived.
// R16: pooling loops (k_final0, k_pf phase-2) rebuilt with boundary fast-path
//      (branch-free unrolled sums for blocks inside one graph) + 256 threads
//      (row-stride 4). R15 gather/GEMM/CSR unchanged.

#define H 128
#define HW 64          // half2 words per row
#define MAXN 50176
#define MAXE 786432
#define MAXLAY 8
#define MAXG 128
#define NSLOT (3 * MAXLAY)
#define BN_EPS 1e-5f

__device__ uint32_t g_h16[MAXN * HW];
__device__ uint32_t g_x16[MAXN * HW];   // h_in16 -> neigh -> t -> u -> v
__device__ uint32_t g_w16[(2 * MAXLAY + 1) * 128 * 64];  // swizzled fp16 weights
__device__ float g_sum[NSLOT * H];
__device__ float g_sq[NSLOT * H];
__device__ float g_pooled[(MAXLAY + 1) * MAXG * H];
__device__ int g_off[MAXN + 1];
__device__ int g_cur[MAXN];
__device__ int g_bsum[64];
__device__ int g_csrc[MAXE];
__device__ volatile unsigned g_bar[MAXLAY];
__device__ volatile unsigned g_cbar[4];

__device__ __forceinline__ uint32_t pack_h2(float x0, float x1) {
    __half2 p = __floats2half2_rn(x0, x1);
    return *(uint32_t*)&p;
}
__device__ __forceinline__ float2 unpack_h2(uint32_t w) {
    return __half22float2(*(__half2*)&w);
}
__device__ __forceinline__ uint32_t hadd2_u(uint32_t a, uint32_t b) {
    __half2 r = __hadd2(*(__half2*)&a, *(__half2*)&b);
    return *(uint32_t*)&r;
}
__device__ __forceinline__ uint32_t bnrelu_h2(uint32_t v, uint32_t sc, uint32_t sh) {
    __half2 r = __hfma2(*(__half2*)&v, *(__half2*)&sc, *(__half2*)&sh);
    r = __hmax2(r, __float2half2_rn(0.f));
    return *(uint32_t*)&r;
}

// ---------------------------------------------------------------------------
__global__ void k_prep(const float* __restrict__ X,
                       const float* __restrict__ embW, const float* __restrict__ W1,
                       const float* __restrict__ W2, int L,
                       int cvtTot, int npool, int nstat, int ncnt) {
    int idx = blockIdx.x * blockDim.x + threadIdx.x;
    if (idx < cvtTot) {
        float2 f = ((const float2*)X)[idx];
        g_x16[idx] = pack_h2(f.x, f.y);
    }
    int wtot = (2 * L + 1) * 8192;
    if (idx < wtot) {
        int mat = idx >> 13;
        int r = idx & 8191;
        int n = r & 127;
        int kp = r >> 7;
        const float* W;
        if (mat == 0) W = embW;
        else if (mat <= L) W = W1 + (size_t)(mat - 1) * H * H;
        else W = W2 + (size_t)(mat - 1 - L) * H * H;
        float f0 = W[(size_t)(2 * kp) * H + n];
        float f1 = W[(size_t)(2 * kp + 1) * H + n];
        int phys = ((((kp >> 2) ^ (n & 7)) << 2) | (kp & 3));
        g_w16[mat * 8192 + n * 64 + phys] = pack_h2(f0, f1);
    }
    if (idx < npool) g_pooled[idx] = 0.f;
    if (idx < nstat) { g_sum[idx] = 0.f; g_sq[idx] = 0.f; }
    if (idx < ncnt) g_off[idx] = 0;
    if (idx < MAXLAY) g_bar[idx] = 0u;
    if (idx < 4) g_cbar[idx] = 0u;
}

// ---------------------------------------------------------------------------
__device__ __forceinline__ void csr_bar(int idx, int nblk) {
    __syncthreads();
    if (threadIdx.x == 0) {
        __threadfence();
        atomicAdd((unsigned*)&g_cbar[idx], 1u);
        while (g_cbar[idx] < (unsigned)nblk) __nanosleep(64);
    }
    __syncthreads();
}

__global__ void __launch_bounds__(1024) k_csr(const int* __restrict__ src,
                                              const int* __restrict__ dst,
                                              int N, int E) {
    __shared__ int s[1024];
    __shared__ int boff;
    const int tid = threadIdx.x;
    const int b = blockIdx.x;
    const int NB = gridDim.x;
    const int stride = NB * 1024;

    for (int e = b * 1024 + tid; e < E; e += stride)
        atomicAdd(&g_off[dst[e]], 1);
    csr_bar(0, NB);

    int idx = b * 1024 + tid;
    int v = (idx < N) ? g_off[idx] : 0;
    s[tid] = v;
    __syncthreads();
#pragma unroll
    for (int off = 1; off < 1024; off <<= 1) {
        int t = (tid >= off) ? s[tid - off] : 0;
        __syncthreads();
        s[tid] += t;
        __syncthreads();
    }
    int incl = s[tid];
    if (tid == 1023) g_bsum[b] = s[1023];
    csr_bar(1, NB);

    if (tid == 0) {
        int o = 0;
        for (int j = 0; j < b; j++) o += *(volatile int*)&g_bsum[j];
        boff = o;
    }
    __syncthreads();
    if (idx < N) {
        int o = incl - v + boff;
        g_off[idx] = o;
        g_cur[idx] = o;
    }
    if (b == 0 && tid == 0) g_off[N] = E;
    csr_bar(2, NB);

    for (int e = b * 1024 + tid; e < E; e += stride) {
        int pos = atomicAdd(&g_cur[dst[e]], 1);
        g_csrc[pos] = src[e];
    }
}

// ---------------------------------------------------------------------------
// gather (R15): warp per 2 dst rows; pairwise HADD2 pre-reduction.
__global__ void k_gather(const float* __restrict__ eps, int layer, int N) {
    int wid = (blockIdx.x * blockDim.x + threadIdx.x) >> 5;
    int lane = threadIdx.x & 31;
    int d0 = 2 * wid;
    if (d0 >= N) return;
    int d1 = d0 + 1;
    bool has1 = (d1 < N);
    float c0 = 1.f + eps[layer];
    const uint2* hp = (const uint2*)g_h16;

    uint2 w0 = hp[d0 * 32 + lane];
    float2 p00 = unpack_h2(w0.x), p01 = unpack_h2(w0.y);
    float4 acc0 = make_float4(p00.x * c0, p00.y * c0, p01.x * c0, p01.y * c0);
    float4 acc1 = make_float4(0.f, 0.f, 0.f, 0.f);
    if (has1) {
        uint2 w1 = hp[d1 * 32 + lane];
        float2 p10 = unpack_h2(w1.x), p11 = unpack_h2(w1.y);
        acc1 = make_float4(p10.x * c0, p10.y * c0, p11.x * c0, p11.y * c0);
    }

    int e0 = g_off[d0], e0e = g_off[d0 + 1];
    int e1 = has1 ? e0e : 0, e1e = has1 ? g_off[d1 + 1] : 0;

    while (e0 + 1 < e0e && e1 + 1 < e1e) {
        int sA = g_csrc[e0], sB = g_csrc[e0 + 1];
        int sC = g_csrc[e1], sD = g_csrc[e1 + 1];
        uint2 vA = hp[sA * 32 + lane];
        uint2 vB = hp[sB * 32 + lane];
        uint2 vC = hp[sC * 32 + lane];
        uint2 vD = hp[sD * 32 + lane];
        uint32_t hx0 = hadd2_u(vA.x, vB.x), hy0 = hadd2_u(vA.y, vB.y);
        uint32_t hx1 = hadd2_u(vC.x, vD.x), hy1 = hadd2_u(vC.y, vD.y);
        float2 f0 = unpack_h2(hx0), f1 = unpack_h2(hy0);
        float2 f2 = unpack_h2(hx1), f3 = unpack_h2(hy1);
        acc0.x += f0.x; acc0.y += f0.y; acc0.z += f1.x; acc0.w += f1.y;
        acc1.x += f2.x; acc1.y += f2.y; acc1.z += f3.x; acc1.w += f3.y;
        e0 += 2; e1 += 2;
    }
    for (; e0 + 1 < e0e; e0 += 2) {
        int sA = g_csrc[e0], sB = g_csrc[e0 + 1];
        uint2 vA = hp[sA * 32 + lane];
        uint2 vB = hp[sB * 32 + lane];
        uint32_t hx = hadd2_u(vA.x, vB.x), hy = hadd2_u(vA.y, vB.y);
        float2 f0 = unpack_h2(hx), f1 = unpack_h2(hy);
        acc0.x += f0.x; acc0.y += f0.y; acc0.z += f1.x; acc0.w += f1.y;
    }
    if (e0 < e0e) {
        int s = g_csrc[e0];
        uint2 v = hp[s * 32 + lane];
        float2 b0 = unpack_h2(v.x), b1 = unpack_h2(v.y);
        acc0.x += b0.x; acc0.y += b0.y; acc0.z += b1.x; acc0.w += b1.y;
    }
    for (; e1 + 1 < e1e; e1 += 2) {
        int sA = g_csrc[e1], sB = g_csrc[e1 + 1];
        uint2 vA = hp[sA * 32 + lane];
        uint2 vB = hp[sB * 32 + lane];
        uint32_t hx = hadd2_u(vA.x, vB.x), hy = hadd2_u(vA.y, vB.y);
        float2 f0 = unpack_h2(hx), f1 = unpack_h2(hy);
        acc1.x += f0.x; acc1.y += f0.y; acc1.z += f1.x; acc1.w += f1.y;
    }
    if (e1 < e1e) {
        int s = g_csrc[e1];
        uint2 v = hp[s * 32 + lane];
        float2 b0 = unpack_h2(v.x), b1 = unpack_h2(v.y);
        acc1.x += b0.x; acc1.y += b0.y; acc1.z += b1.x; acc1.w += b1.y;
    }

    uint2 o0;
    o0.x = pack_h2(acc0.x, acc0.y);
    o0.y = pack_h2(acc0.z, acc0.w);
    ((uint2*)g_x16)[d0 * 32 + lane] = o0;
    if (has1) {
        uint2 o1;
        o1.x = pack_h2(acc1.x, acc1.y);
        o1.y = pack_h2(acc1.z, acc1.w);
        ((uint2*)g_x16)[d1 * 32 + lane] = o1;
    }
}

// ---------------------------------------------------------------------------
// Persistent pipelined tensor-core GEMM (fp16 in/out, fp32 accum). (R12)

#define SM_B 16384
#define SM_STAT 24576
#define GSMEM_TC ((24576 + 512) * 4)

#define MMA_F16(d, a0, a1, a2, a3, b0, b1)                                   \
    asm volatile(                                                            \
        "mma.sync.aligned.m16n8k16.row.col.f32.f16.f16.f32 "                 \
        "{%0,%1,%2,%3}, {%4,%5,%6,%7}, {%8,%9}, {%0,%1,%2,%3};"              \
        : "+f"(d[0]), "+f"(d[1]), "+f"(d[2]), "+f"(d[3])                     \
        : "r"(a0), "r"(a1), "r"(a2), "r"(a3), "r"(b0), "r"(b1))

#define LDSM4(r0, r1, r2, r3, addr)                                          \
    asm volatile("ldmatrix.sync.aligned.m8n8.x4.shared.b16 {%0,%1,%2,%3}, [%4];" \
                 : "=r"(r0), "=r"(r1), "=r"(r2), "=r"(r3) : "r"(addr))

__device__ __forceinline__ void prefetchA(uint32_t dstBase, const uint32_t* __restrict__ A16,
                                          int m0, int N, int tid) {
#pragma unroll
    for (int i = 0; i < 8; i++) {
        int idx = tid + i * 256;
        int row = idx >> 4;
        int c = idx & 15;
        int gm = m0 + row;
        if (gm > N - 1) gm = N - 1;
        uint32_t dst = dstBase + (uint32_t)(row * 64 + ((c ^ (row & 7)) << 2)) * 4;
        const uint32_t* src = A16 + (size_t)gm * HW + c * 4;
        asm volatile("cp.async.cg.shared.global [%0], [%1], 16;" :: "r"(dst), "l"(src));
    }
    asm volatile("cp.async.commit_group;");
}

__global__ void __launch_bounds__(256, 2) k_gemm_tc(
    const uint32_t* __restrict__ A16,
    const float* __restrict__ gamma, const float* __restrict__ beta, int ssIn,
    int wslot, const float* __restrict__ bias,
    uint32_t* __restrict__ C16, int outSlot, int N, int ntiles) {
    extern __shared__ uint32_t sm32[];
    uint32_t* Bs = sm32 + SM_B;
    float* ssum = (float*)(sm32 + SM_STAT);
    float* ssq = ssum + 128;
    uint32_t* scs = (uint32_t*)(ssq + 128);
    uint32_t* shs = scs + 64;

    const int tid = threadIdx.x;
    const int doBN = (ssIn >= 0);

    if (outSlot >= 0 && tid < 128) { ssum[tid] = 0.f; ssq[tid] = 0.f; }
    if (doBN && tid < 64) {
        float invN = 1.f / (float)N;
        int k0 = 2 * tid, k1 = k0 + 1;
        float m0 = g_sum[ssIn * H + k0] * invN;
        float v0 = g_sq[ssIn * H + k0] * invN - m0 * m0;
        float r0 = rsqrtf(v0 + BN_EPS);
        float sc0 = gamma[k0] * r0, sh0 = beta[k0] - m0 * sc0;
        float m1 = g_sum[ssIn * H + k1] * invN;
        float v1 = g_sq[ssIn * H + k1] * invN - m1 * m1;
        float r1 = rsqrtf(v1 + BN_EPS);
        float sc1 = gamma[k1] * r1, sh1 = beta[k1] - m1 * sc1;
        scs[tid] = pack_h2(sc0, sc1);
        shs[tid] = pack_h2(sh0, sh1);
    }

    {
        const uint4* Wm = (const uint4*)(g_w16 + wslot * 8192);
        uint4* Bd = (uint4*)Bs;
#pragma unroll
        for (int i = 0; i < 8; i++) Bd[tid + i * 256] = Wm[tid + i * 256];
    }

    const int w = tid >> 5;
    const int l = tid & 31;
    const int rb = (w & 3) * 32;
    const int cb = (w >> 2) * 64;
    const int c3 = l & 3;

    const uint32_t sbase = (uint32_t)__cvta_generic_to_shared(sm32);
    const uint32_t bBase = sbase + SM_B * 4;

    const int a_r = l & 15;
    const int a_c = l >> 4;
    const int b_nl = ((l >> 4) << 3) + (l & 7);
    const int b_kl = (l >> 3) & 1;

    int buf = 0;
    if (blockIdx.x < ntiles)
        prefetchA(sbase, A16, blockIdx.x * 128, N, tid);

    for (int tile = blockIdx.x; tile < ntiles; tile += gridDim.x) {
        const int m0 = tile * 128;
        int nxt = tile + gridDim.x;
        if (nxt < ntiles) {
            prefetchA(sbase + (buf ^ 1) * 8192 * 4, A16, nxt * 128, N, tid);
            asm volatile("cp.async.wait_group 1;");
        } else {
            asm volatile("cp.async.wait_group 0;");
        }
        __syncthreads();

        const uint32_t aBase = sbase + (uint32_t)buf * 8192 * 4;

        float acc[2][8][4];
#pragma unroll
        for (int mt = 0; mt < 2; mt++)
#pragma unroll
            for (int nt = 0; nt < 8; nt++)
#pragma unroll
                for (int j = 0; j < 4; j++) acc[mt][nt][j] = 0.f;

#pragma unroll
        for (int ks = 0; ks < 8; ks++) {
            uint32_t a[2][4];
#pragma unroll
            for (int mt = 0; mt < 2; mt++) {
                int row = rb + mt * 16 + a_r;
                int kc = ks * 2 + a_c;
                uint32_t addr = aBase + (row * 64 + ((kc ^ (row & 7)) << 2)) * 4;
                LDSM4(a[mt][0], a[mt][1], a[mt][2], a[mt][3], addr);
            }
            if (doBN) {
                uint32_t scA = scs[ks * 8 + c3], shA = shs[ks * 8 + c3];
                uint32_t scB = scs[ks * 8 + 4 + c3], shB = shs[ks * 8 + 4 + c3];
#pragma unroll
                for (int mt = 0; mt < 2; mt++) {
                    a[mt][0] = bnrelu_h2(a[mt][0], scA, shA);
                    a[mt][1] = bnrelu_h2(a[mt][1], scA, shA);
                    a[mt][2] = bnrelu_h2(a[mt][2], scB, shB);
                    a[mt][3] = bnrelu_h2(a[mt][3], scB, shB);
                }
            }
            uint32_t b[4][4];
#pragma unroll
            for (int np = 0; np < 4; np++) {
                int n = cb + np * 16 + b_nl;
                int kc = ks * 2 + b_kl;
                uint32_t addr = bBase + (n * 64 + ((kc ^ (n & 7)) << 2)) * 4;
                LDSM4(b[np][0], b[np][1], b[np][2], b[np][3], addr);
            }
#pragma unroll
            for (int mt = 0; mt < 2; mt++)
#pragma unroll
                for (int np = 0; np < 4; np++) {
                    MMA_F16(acc[mt][np * 2], a[mt][0], a[mt][1], a[mt][2], a[mt][3],
                            b[np][0], b[np][1]);
                    MMA_F16(acc[mt][np * 2 + 1], a[mt][0], a[mt][1], a[mt][2], a[mt][3],
                            b[np][2], b[np][3]);
                }
        }

#pragma unroll
        for (int mt = 0; mt < 2; mt++) {
            const int r0 = m0 + rb + mt * 16 + (l >> 2);
            const int r1 = r0 + 8;
#pragma unroll
            for (int nt = 0; nt < 8; nt++) {
                int c0 = cb + nt * 8 + (l & 3) * 2;
                float bb0 = bias[c0], bb1 = bias[c0 + 1];
                float v0 = acc[mt][nt][0] + bb0;
                float v1 = acc[mt][nt][1] + bb1;
                float v2 = acc[mt][nt][2] + bb0;
                float v3 = acc[mt][nt][3] + bb1;
                int wIdx = c0 >> 1;
                if (r0 < N) C16[(size_t)r0 * HW + wIdx] = pack_h2(v0, v1);
                if (r1 < N) C16[(size_t)r1 * HW + wIdx] = pack_h2(v2, v3);
                if (outSlot >= 0) {
                    float s0 = (r0 < N ? v0 : 0.f) + (r1 < N ? v2 : 0.f);
                    float s1 = (r0 < N ? v1 : 0.f) + (r1 < N ? v3 : 0.f);
                    float q0 = (r0 < N ? v0 * v0 : 0.f) + (r1 < N ? v2 * v2 : 0.f);
                    float q1 = (r0 < N ? v1 * v1 : 0.f) + (r1 < N ? v3 * v3 : 0.f);
#pragma unroll
                    for (int off = 16; off >= 4; off >>= 1) {
                        s0 += __shfl_down_sync(0xffffffffu, s0, off);
                        s1 += __shfl_down_sync(0xffffffffu, s1, off);
                        q0 += __shfl_down_sync(0xffffffffu, q0, off);
                        q1 += __shfl_down_sync(0xffffffffu, q1, off);
                    }
                    if (l < 4) {
                        atomicAdd(&ssum[c0], s0);
                        atomicAdd(&ssum[c0 + 1], s1);
                        atomicAdd(&ssq[c0], q0);
                        atomicAdd(&ssq[c0 + 1], q1);
                    }
                }
            }
        }
        __syncthreads();
        buf ^= 1;
    }
    if (outSlot >= 0) {
        if (tid < 128) {
            atomicAdd(&g_sum[outSlot * H + tid], ssum[tid]);
            atomicAdd(&g_sq[outSlot * H + tid], ssq[tid]);
        }
    }
}

// ---------------------------------------------------------------------------
// Fused passv + final (persistent, grid barrier); 256 threads, stride-4 rows.
// Phase 2 uses a boundary fast-path (branch-free) when the block's row range
// lies inside one graph.
__global__ void __launch_bounds__(256) k_pf(
    uint32_t* __restrict__ X16, const float* __restrict__ snorm,
    const float* __restrict__ ga, const float* __restrict__ ba,
    const float* __restrict__ gl, const float* __restrict__ bl,
    const int* __restrict__ gids, int sIn, int sOut, int layer,
    int rep, int NG, int N, int nblk) {
    const int w = threadIdx.x & 63;
    const int rh = threadIdx.x >> 6;     // 0..3
    const int c0 = 2 * w, c1 = c0 + 1;
    const float invN = 1.f / (float)N;

    const int chunk = (N + nblk - 1) / nblk;
    const int nb = blockIdx.x * chunk;
    const int ne = (nb + chunk < N) ? nb + chunk : N;

    // ---- Phase 1: x = snorm * relu(bn_a(x)), stats -> sOut ----
    {
        float m0 = g_sum[sIn * H + c0] * invN;
        float v0 = g_sq[sIn * H + c0] * invN - m0 * m0;
        float r0 = rsqrtf(v0 + BN_EPS);
        float sc0 = ga[c0] * r0, sh0 = ba[c0] - m0 * sc0;
        float m1 = g_sum[sIn * H + c1] * invN;
        float v1 = g_sq[sIn * H + c1] * invN - m1 * m1;
        float r1 = rsqrtf(v1 + BN_EPS);
        float sc1 = ga[c1] * r1, sh1 = ba[c1] - m1 * sc1;

        float s0 = 0.f, s1 = 0.f, q0 = 0.f, q1 = 0.f;
        for (int n = nb + rh; n < ne; n += 4) {
            float sn = snorm[n];
            float2 f = unpack_h2(X16[n * HW + w]);
            float x0 = fmaxf(sc0 * f.x + sh0, 0.f) * sn;
            float x1 = fmaxf(sc1 * f.y + sh1, 0.f) * sn;
            X16[n * HW + w] = pack_h2(x0, x1);
            s0 += x0; s1 += x1; q0 += x0 * x0; q1 += x1 * x1;
        }
        atomicAdd(&g_sum[sOut * H + c0], s0);
        atomicAdd(&g_sum[sOut * H + c1], s1);
        atomicAdd(&g_sq[sOut * H + c0], q0);
        atomicAdd(&g_sq[sOut * H + c1], q1);
    }

    __syncthreads();
    if (threadIdx.x == 0) {
        __threadfence();
        atomicAdd((unsigned*)&g_bar[layer], 1u);
        while (g_bar[layer] < (unsigned)nblk) __nanosleep(64);
    }
    __syncthreads();

    // ---- Phase 2: h += relu(bn_l(x)); pool ----
    {
        float sum0 = __ldcg((const float*)&g_sum[sOut * H + c0]);
        float sum1 = __ldcg((const float*)&g_sum[sOut * H + c1]);
        float sq0 = __ldcg((const float*)&g_sq[sOut * H + c0]);
        float sq1 = __ldcg((const float*)&g_sq[sOut * H + c1]);
        float m0 = sum0 * invN;
        float v0 = sq0 * invN - m0 * m0;
        float r0 = rsqrtf(v0 + BN_EPS);
        float sc0 = gl[c0] * r0, sh0 = bl[c0] - m0 * sc0;
        float m1 = sum1 * invN;
        float v1 = sq1 * invN - m1 * m1;
        float r1 = rsqrtf(v1 + BN_EPS);
        float sc1 = gl[c1] * r1, sh1 = bl[c1] - m1 * sc1;

        float* pooled = g_pooled + (size_t)rep * NG * H;
        if (nb < ne) {
            int gF = gids[nb], gL = gids[ne - 1];
            if (gF == gL) {
                // fast path: branch-free, loads independent
                float a0 = 0.f, a1 = 0.f;
                for (int n = nb + rh; n < ne; n += 4) {
                    float2 hv = unpack_h2(g_h16[n * HW + w]);
                    float2 f = unpack_h2(X16[n * HW + w]);
                    hv.x += fmaxf(sc0 * f.x + sh0, 0.f);
                    hv.y += fmaxf(sc1 * f.y + sh1, 0.f);
                    g_h16[n * HW + w] = pack_h2(hv.x, hv.y);
                    a0 += hv.x; a1 += hv.y;
                }
                atomicAdd(&pooled[gF * H + c0], a0);
                atomicAdd(&pooled[gF * H + c1], a1);
            } else {
                float a0 = 0.f, a1 = 0.f;
                int curg = gids[nb + rh < ne ? nb + rh : nb];
                for (int n = nb + rh; n < ne; n += 4) {
                    int g = gids[n];
                    if (g != curg) {
                        atomicAdd(&pooled[curg * H + c0], a0);
                        atomicAdd(&pooled[curg * H + c1], a1);
                        a0 = 0.f; a1 = 0.f;
                        curg = g;
                    }
                    float2 hv = unpack_h2(g_h16[n * HW + w]);
                    float2 f = unpack_h2(X16[n * HW + w]);
                    hv.x += fmaxf(sc0 * f.x + sh0, 0.f);
                    hv.y += fmaxf(sc1 * f.y + sh1, 0.f);
                    g_h16[n * HW + w] = pack_h2(hv.x, hv.y);
                    a0 += hv.x; a1 += hv.y;
                }
                atomicAdd(&pooled[curg * H + c0], a0);
                atomicAdd(&pooled[curg * H + c1], a1);
            }
        }
    }
}

// pool for hidden_rep[0] (fp16 h); 256 threads, 128 rows/block, fast-path.
__global__ void __launch_bounds__(256) k_final0(const int* __restrict__ gids,
                                                int NG, int N) {
    int w = threadIdx.x & 63;
    int rh = threadIdx.x >> 6;           // 0..3
    int c0 = 2 * w, c1 = c0 + 1;
    int nb = blockIdx.x * 128;
    if (nb >= N) return;
    int ne = nb + 128 < N ? nb + 128 : N;
    int gF = gids[nb], gL = gids[ne - 1];
    if (gF == gL) {
        float a0 = 0.f, a1 = 0.f;
        for (int n = nb + rh; n < ne; n += 4) {
            float2 hv = unpack_h2(g_h16[n * HW + w]);
            a0 += hv.x; a1 += hv.y;
        }
        atomicAdd(&g_pooled[gF * H + c0], a0);
        atomicAdd(&g_pooled[gF * H + c1], a1);
    } else {
        float a0 = 0.f, a1 = 0.f;
        int curg = gids[nb + rh < ne ? nb + rh : nb];
        for (int n = nb + rh; n < ne; n += 4) {
            int g = gids[n];
            if (g != curg) {
                atomicAdd(&g_pooled[curg * H + c0], a0);
                atomicAdd(&g_pooled[curg * H + c1], a1);
                a0 = 0.f; a1 = 0.f;
                curg = g;
            }
            float2 hv = unpack_h2(g_h16[n * HW + w]);
            a0 += hv.x; a1 += hv.y;
        }
        atomicAdd(&g_pooled[curg * H + c0], a0);
        atomicAdd(&g_pooled[curg * H + c1], a1);
    }
}

__global__ void k_score(const float* __restrict__ predW, const float* __restrict__ predb,
                        float* __restrict__ out, int NG, int C, int nrep) {
    int g = blockIdx.x;
    int c = threadIdx.x;
    if (c >= C) return;
    float s = 0.f;
    for (int rep = 0; rep < nrep; rep++) {
        const float* pl = g_pooled + ((size_t)rep * NG + g) * H;
        const float* W = predW + (size_t)rep * H * C;
        float acc = 0.f;
        for (int k = 0; k < H; k++) acc = fmaf(pl[k], W[k * C + c], acc);
        s += acc + predb[rep * C + c];
    }
    out[g * C + c] = s;
}

// ---------------------------------------------------------------------------
extern "C" void kernel_launch(void* const* d_in, const int* in_sizes, int n_in,
                              void* d_out, int out_size) {
    const float* h_in  = (const float*)d_in[0];
    const float* snorm = (const float*)d_in[1];
    const int* esrc    = (const int*)d_in[2];
    const int* edst    = (const int*)d_in[3];
    const int* gids    = (const int*)d_in[4];
    const float* embW  = (const float*)d_in[5];
    const float* embb  = (const float*)d_in[6];
    const float* eps   = (const float*)d_in[7];
    const float* W1    = (const float*)d_in[8];
    const float* b1    = (const float*)d_in[9];
    const float* g1    = (const float*)d_in[10];
    const float* be1   = (const float*)d_in[11];
    const float* W2    = (const float*)d_in[12];
    const float* b2    = (const float*)d_in[13];
    const float* ga    = (const float*)d_in[14];
    const float* ba    = (const float*)d_in[15];
    const float* gl    = (const float*)d_in[16];
    const float* bl    = (const float*)d_in[17];
    const float* predW = (const float*)d_in[18];
    const float* predb = (const float*)d_in[19];
    float* out = (float*)d_out;

    int N = in_sizes[0] / H;
    int E = in_sizes[2];
    int L = in_sizes[7];
    int C = in_sizes[19] / (L + 1);
    int NG = out_size / C;
    int NB = (N + 1023) / 1024;

    cudaFuncSetAttribute(k_gemm_tc, cudaFuncAttributeMaxDynamicSharedMemorySize, GSMEM_TC);

    uint32_t *p_h16, *p_x16;
    cudaGetSymbolAddress((void**)&p_h16, g_h16);
    cudaGetSymbolAddress((void**)&p_x16, g_x16);

    int smCount = 148, occBlocks = 8;
    cudaDeviceGetAttribute(&smCount, cudaDevAttrMultiProcessorCount, 0);
    cudaOccupancyMaxActiveBlocksPerMultiprocessor(&occBlocks, k_pf, 256, 0);
    if (occBlocks < 1) occBlocks = 1;
    if (occBlocks > 8) occBlocks = 8;
    int nblk = smCount * occBlocks;

    int ntiles = (N + 127) / 128;
    int gemmGrid = 2 * smCount;
    if (gemmGrid > ntiles) gemmGrid = ntiles;
    int rowGrid = ntiles;

    int npool = (L + 1) * NG * H;
    int nstat = 3 * L * H;
    int ncnt = N + 1;
    int cvtTot = N * HW;

    int gwarps = (N + 1) / 2;
    int gblocks = (gwarps * 32 + 255) / 256;

    // Launch order: index 3 (ncu capture slot) = k_final0.
    k_prep<<<(cvtTot + 255) / 256, 256>>>(h_in, embW, W1, W2, L,
                                          cvtTot, npool, nstat, ncnt);      // 0
    k_csr<<<NB, 1024>>>(esrc, edst, N, E);                                  // 1
    k_gemm_tc<<<gemmGrid, 256, GSMEM_TC>>>(p_x16, nullptr, nullptr, -1,
                                           0, embb, p_h16, -1, N, ntiles);  // 2 (emb)
    k_final0<<<rowGrid, 256>>>(gids, NG, N);                                // 3 <- capture
    k_gather<<<gblocks, 256>>>(eps, 0, N);                                  // 4

    for (int i = 0; i < L; i++) {
        int s0 = 3 * i, s1 = 3 * i + 1, s2 = 3 * i + 2;
        k_gemm_tc<<<gemmGrid, 256, GSMEM_TC>>>(p_x16, nullptr, nullptr, -1,
                                               1 + i, b1 + i * H,
                                               p_x16, s0, N, ntiles);
        k_gemm_tc<<<gemmGrid, 256, GSMEM_TC>>>(p_x16, g1 + i * H, be1 + i * H, s0,
                                               1 + L + i, b2 + i * H,
                                               p_x16, s1, N, ntiles);
        k_pf<<<nblk, 256>>>(p_x16, snorm, ga + i * H, ba + i * H,
                            gl + i * H, bl + i * H, gids,
                            s1, s2, i, i + 1, NG, N, nblk);
        if (i + 1 < L)
            k_gather<<<gblocks, 256>>>(eps, i + 1, N);
    }

    k_score<<<NG, 32>>>(predW, predb, out, NG, C, L + 1);
}